// round 11
// baseline (speedup 1.0000x reference)
#include <cuda_runtime.h>

// MBTR + analytic divergence, GB300 (sm_103a). Round 9:
//   R8 layout (warp=atom, lane=g, 48-bit band mask) plus:
//   - manually software-pipelined ffs loop (compiler can't pipeline a
//     data-dependent while; prefetch next pair's table entry before the
//     current FP chain so LDS(29cyc)+MUFU(16cyc) overlap)
//   - div epilogue via slot-layout smem (zero-init STS.128, direct segment
//     writes, float4 copy-out) instead of per-cell select+scatter
//   - BAND 5.5 sigma; float4 zero kernel

#define NB   32
#define NA   48
#define NE   4
#define NG   128
#define ATH  8                  // atoms per block
#define GC   32                 // grid points per block (one warp-lane each)
#define NTHR (ATH * GC)         // 256
#define NTHIRD (NA / ATH)       // 6
#define NGCH   (NG / GC)        // 4
#define NBLK (NB * NGCH * NTHIRD)   // 768
#define MBTR_SZ (NB * NE * NE * NG) // 65536
#define ROWQ (ATH * 3)          // 24 floats per (slot,g) row owned by block
#define DIVPAD 25               // pad: stride 25 coprime with 32 banks

static __device__ __forceinline__ float ex2f(float x) {
    float y;
    asm("ex2.approx.ftz.f32 %0, %1;" : "=f"(y) : "f"(x));
    return y;
}

__global__ void zero_mbtr(float4* __restrict__ out) {
    out[blockIdx.x * 1024 + threadIdx.x] = make_float4(0.f, 0.f, 0.f, 0.f);
}

__global__ void __launch_bounds__(NTHR, 3)
mbtr_kernel(const float* __restrict__ r,
            const int*   __restrict__ z,
            const float* __restrict__ grid,
            float*       __restrict__ out)
{
    const int bid    = blockIdx.x;
    const int third  = bid % NTHIRD;
    const int tmp    = bid / NTHIRD;
    const int gchunk = tmp % NGCH;
    const int b      = tmp / NGCH;

    const int t    = threadIdx.x;
    const int al   = t >> 5;            // warp id = local atom
    const int lane = t & 31;
    const int a    = third * ATH + al;  // global atom
    const int g    = gchunk * GC + lane;

    __shared__ float4 tabA[NA][ATH];    // {gfs, wf*C, gsq, -ux}
    __shared__ float2 tabB[NA][ATH];    // {-uy, -uz}
    __shared__ float  gfsT[ATH][NA];    // gfs, lane-major readable
    __shared__ float  sm_div[NE * NE][GC][DIVPAD];
    __shared__ float4 rs[NA];
    __shared__ int    zs[NA], S[NA], segs[NE + 1];

    const float INV_SIGMA = 20.0f;
    const float CM        = -0.72134752044448170f;   // -0.5 * log2(e)
    const float BAND      = 5.5f;                    // sigma units

    // Zero the slot-layout div buffer (16*32*25 = 12800 floats = 3200 f4).
    {
        float4* zf = (float4*)&sm_div[0][0][0];
        const float4 z4 = make_float4(0.f, 0.f, 0.f, 0.f);
        #pragma unroll
        for (int i = 0; i < 13; i++) {
            const int idx = i * NTHR + t;
            if (idx < 3200) zf[idx] = z4;
        }
    }

    if (t < NA) {
        zs[t] = z[t];
        const float* rp = r + (b * NA + t) * 3;
        rs[t] = make_float4(rp[0], rp[1], rp[2], 0.f);
    }
    __syncthreads();

    if (t == 0) {
        int cnt[NE] = {0, 0, 0, 0};
        for (int j = 0; j < NA; j++) cnt[zs[j]]++;
        int off = 0, pos[NE];
        segs[0] = 0;
        #pragma unroll
        for (int e = 0; e < NE; e++) { pos[e] = off; off += cnt[e]; segs[e + 1] = off; }
        for (int j = 0; j < NA; j++) S[pos[zs[j]]++] = j;
    }
    __syncthreads();

    // Pair table: 48 partners x 8 local atoms = 384 entries over 256 threads.
    {
        const float gdx = grid[1] - grid[0];
        const float C   = gdx * 0.3989422804014327f * INV_SIGMA;
        for (int f = t; f < NA * ATH; f += NTHR) {
            const int jp  = f >> 3;
            const int al2 = f & (ATH - 1);
            const int a2  = third * ATH + al2;
            const int p   = S[jp];
            if (p == a2) {
                tabA[jp][al2] = make_float4(0.f, 0.f, 0.f, 0.f);
                tabB[jp][al2] = make_float2(0.f, 0.f);
                gfsT[al2][jp] = 0.f;
            } else {
                const float4 ra = rs[a2], rp = rs[p];
                const float dx = ra.x - rp.x, dy = ra.y - rp.y, dz = ra.z - rp.z;
                const float d2   = fmaf(dx, dx, fmaf(dy, dy, dz * dz));
                const float invd = rsqrtf(d2);
                const float d    = d2 * invd;
                const float wf   = __expf(-d);
                const float gfs  = invd * INV_SIGMA;
                tabA[jp][al2] = make_float4(gfs, wf * C,
                                            invd * invd * INV_SIGMA, -dx * invd);
                tabB[jp][al2] = make_float2(-dy * invd, -dz * invd);
                gfsT[al2][jp] = gfs;
            }
        }
    }
    __syncthreads();

    const int   za = zs[a];
    const float gg = grid[g] * INV_SIGMA;
    const float bandlo = __shfl_sync(0xffffffffu, gg, 0)  - BAND;
    const float bandhi = __shfl_sync(0xffffffffu, gg, 31) + BAND;

    // 48-bit active-pair mask (warp-uniform).
    const float f0 = gfsT[al][lane];
    const unsigned m0 = __ballot_sync(0xffffffffu, f0 > bandlo && f0 < bandhi);
    const float f1 = (lane < 16) ? gfsT[al][32 + lane] : 0.f;
    const unsigned m1 = __ballot_sync(0xffffffffu,
                                      lane < 16 && f1 > bandlo && f1 < bandhi);
    const unsigned long long mask =
        (unsigned long long)m0 | ((unsigned long long)(m1 & 0xFFFFu) << 32);

    float* const mb = out + (((b * NE + za) * NE) * NG) + g;
    const int q3 = al * 3;

    #pragma unroll
    for (int e = 0; e < NE; e++) {
        unsigned long long m =
            mask & ((1ull << segs[e + 1]) - (1ull << segs[e]));
        if (!m) continue;      // zero-init already covers the slots

        float wv = 0.f, xv = 0.f, yv = 0.f, zv = 0.f;

        // Software-pipelined set-bit iteration.
        int jp = __ffsll((long long)m) - 1;
        m &= m - 1;
        float4 A  = tabA[jp][al];
        float2 Bv = tabB[jp][al];
        while (true) {
            const bool more = (m != 0);
            const int jn = more ? (__ffsll((long long)m) - 1) : jp;
            m &= m - 1;
            const float4 An = tabA[jn][al];     // prefetch (broadcast LDS)
            const float2 Bn = tabB[jn][al];

            const float tt = gg - A.x;
            const float E  = ex2f((CM * tt) * tt);
            const float wg = A.y * E;
            const float s  = fmaf(wg * A.z, tt, wg);
            wv += wg;
            xv = fmaf(s, A.w,  xv);
            yv = fmaf(s, Bv.x, yv);
            zv = fmaf(s, Bv.y, zv);

            if (!more) break;
            A = An; Bv = Bn;
        }

        // mbtr: coalesced RED.ADD per warp per segment.
        atomicAdd(mb + e * NG, wv);

        // Direct slot-layout stash (conflict-free: lane stride 25).
        if (e == za) {
            float* q = &sm_div[za * NE + za][lane][q3];
            q[0] = 2.f * xv; q[1] = 2.f * yv; q[2] = 2.f * zv;
        } else {
            float* q = &sm_div[za * NE + e][lane][q3];
            q[0] = xv; q[1] = yv; q[2] = zv;
            q = &sm_div[e * NE + za][lane][q3];
            q[0] = xv; q[1] = yv; q[2] = zv;
        }
    }
    __syncthreads();

    // Copy-out: 16 slots x 32 g x 24 floats = 3072 float4 -> 12 per thread.
    float* __restrict__ dbase = out + MBTR_SZ
        + ((size_t)(b * NE * NE) * NG + gchunk * GC) * (NA * 3)
        + third * ROWQ;
    #pragma unroll
    for (int k = 0; k < 12; k++) {
        const int off  = (k * NTHR + t) * 4;
        const int slot = off / (GC * ROWQ);
        const int rem  = off - slot * (GC * ROWQ);
        const int g2   = rem / ROWQ;
        const int q    = rem - g2 * ROWQ;
        const float* s = &sm_div[slot][g2][q];
        float4 v;
        v.x = s[0]; v.y = s[1]; v.z = s[2]; v.w = s[3];
        *(float4*)(dbase + (size_t)slot * (NG * NA * 3) + g2 * (NA * 3) + q) = v;
    }
}

extern "C" void kernel_launch(void* const* d_in, const int* in_sizes, int n_in,
                              void* d_out, int out_size)
{
    const float* r    = (const float*)d_in[0];
    const int*   z    = (const int*)  d_in[1];
    const float* grid = (const float*)d_in[2];
    float*       out  = (float*)d_out;

    zero_mbtr<<<MBTR_SZ / 4096, 1024>>>((float4*)out);
    mbtr_kernel<<<NBLK, NTHR>>>(r, z, grid, out);
}

// round 13
// speedup vs baseline: 1.0918x; 1.0918x over previous
#include <cuda_runtime.h>

// MBTR + analytic divergence, GB300 (sm_103a). Round 10 = R8 +
//   (a) inner loop processes 2 set bits per iteration: two independent
//       LDS->FMA->MUFU chains per iteration (ILP x2) with NO state carried
//       across iterations (R9's pipelining failure mode); odd tail handled
//       branchlessly via k1 factor and m&=m-1 on m==0 staying 0.
//   (b) epilogue: per-cell predicate hoisting -> FSEL-based slot writes.
//
// Block = (b, g-chunk of 32, atom-sixth of 8). Warp = one atom, lane = one g.
// Band skip: pair irrelevant unless gfs in [gg_lo-5.5, gg_hi+5.5] sigma.
// Warp-uniform predicate -> 48-bit mask via 2 ballots, iterate set bits.
// mbtr via coalesced global atomicAdd into pre-zeroed region (zero kernel).

#define NB   32
#define NA   48
#define NE   4
#define NG   128
#define ATH  8                  // atoms per block
#define GC   32                 // grid points per block
#define NTHR (ATH * GC)         // 256
#define NTHIRD (NA / ATH)       // 6
#define NGCH   (NG / GC)        // 4
#define NBLK (NB * NGCH * NTHIRD)   // 768
#define MBTR_SZ (NB * NE * NE * NG) // 65536
#define ROWQ (ATH * 3)          // 24 floats per (slot,g) row owned by block
#define ACCPAD (ROWQ + 1)       // 25

static __device__ __forceinline__ float ex2f(float x) {
    float y;
    asm("ex2.approx.ftz.f32 %0, %1;" : "=f"(y) : "f"(x));
    return y;
}

__global__ void zero_mbtr(float4* __restrict__ out) {
    out[blockIdx.x * 1024 + threadIdx.x] = make_float4(0.f, 0.f, 0.f, 0.f);
}

__global__ void __launch_bounds__(NTHR, 4)
mbtr_kernel(const float* __restrict__ r,
            const int*   __restrict__ z,
            const float* __restrict__ grid,
            float*       __restrict__ out)
{
    const int bid    = blockIdx.x;
    const int third  = bid % NTHIRD;
    const int tmp    = bid / NTHIRD;
    const int gchunk = tmp % NGCH;
    const int b      = tmp / NGCH;

    const int t    = threadIdx.x;
    const int al   = t >> 5;            // warp id = local atom
    const int lane = t & 31;
    const int a    = third * ATH + al;  // global atom
    const int g    = gchunk * GC + lane;

    __shared__ float4 tabA[NA][ATH];    // {gfs, wf*C, gsq, -ux}
    __shared__ float2 tabB[NA][ATH];    // {-uy, -uz}
    __shared__ float  gfsT[ATH][NA];    // gfs, lane-major readable
    __shared__ float  acc[NE][GC][ACCPAD];
    __shared__ float4 rs[NA];
    __shared__ int    zs[NA], S[NA], segs[NE + 1];

    const float INV_SIGMA = 20.0f;
    const float CM        = -0.72134752044448170f;   // -0.5 * log2(e)
    const float BAND      = 5.5f;                    // sigma units

    if (t < NA) {
        zs[t] = z[t];
        const float* rp = r + (b * NA + t) * 3;
        rs[t] = make_float4(rp[0], rp[1], rp[2], 0.f);
    }
    __syncthreads();

    if (t == 0) {
        int cnt[NE] = {0, 0, 0, 0};
        for (int j = 0; j < NA; j++) cnt[zs[j]]++;
        int off = 0, pos[NE];
        segs[0] = 0;
        #pragma unroll
        for (int e = 0; e < NE; e++) { pos[e] = off; off += cnt[e]; segs[e + 1] = off; }
        for (int j = 0; j < NA; j++) S[pos[zs[j]]++] = j;
    }
    __syncthreads();

    // Pair table: 48 partners x 8 local atoms = 384 entries over 256 threads.
    {
        const float gdx = grid[1] - grid[0];
        const float C   = gdx * 0.3989422804014327f * INV_SIGMA;
        for (int f = t; f < NA * ATH; f += NTHR) {
            const int jp  = f >> 3;
            const int al2 = f & (ATH - 1);
            const int a2  = third * ATH + al2;
            const int p   = S[jp];
            if (p == a2) {
                tabA[jp][al2] = make_float4(0.f, 0.f, 0.f, 0.f);
                tabB[jp][al2] = make_float2(0.f, 0.f);
                gfsT[al2][jp] = 0.f;
            } else {
                const float4 ra = rs[a2], rp = rs[p];
                const float dx = ra.x - rp.x, dy = ra.y - rp.y, dz = ra.z - rp.z;
                const float d2   = fmaf(dx, dx, fmaf(dy, dy, dz * dz));
                const float invd = rsqrtf(d2);
                const float d    = d2 * invd;
                const float wf   = __expf(-d);
                const float gfs  = invd * INV_SIGMA;
                tabA[jp][al2] = make_float4(gfs, wf * C,
                                            invd * invd * INV_SIGMA, -dx * invd);
                tabB[jp][al2] = make_float2(-dy * invd, -dz * invd);
                gfsT[al2][jp] = gfs;
            }
        }
    }
    __syncthreads();

    const int   za = zs[a];
    const float gg = grid[g] * INV_SIGMA;
    const float bandlo = __shfl_sync(0xffffffffu, gg, 0)  - BAND;
    const float bandhi = __shfl_sync(0xffffffffu, gg, 31) + BAND;

    // 48-bit active-pair mask (warp-uniform).
    const float f0 = gfsT[al][lane];
    const unsigned b0m = __ballot_sync(0xffffffffu, f0 > bandlo && f0 < bandhi);
    const float f1 = (lane < 16) ? gfsT[al][32 + lane] : 0.f;
    const unsigned b1m = __ballot_sync(0xffffffffu,
                                       lane < 16 && f1 > bandlo && f1 < bandhi);
    const unsigned long long mask =
        (unsigned long long)b0m | ((unsigned long long)(b1m & 0xFFFFu) << 32);

    float* const mb = out + (((b * NE + za) * NE) * NG) + g;

    #pragma unroll
    for (int e = 0; e < NE; e++) {
        unsigned long long m =
            mask & ((1ull << segs[e + 1]) - (1ull << segs[e]));
        float wv = 0.f, xv = 0.f, yv = 0.f, zv = 0.f;

        // 2 set bits per iteration: two independent FP chains (ILP x2).
        while (m) {
            const int j0 = __ffsll((long long)m) - 1;
            m &= m - 1;
            const bool two = (m != 0);
            const int j1 = two ? (__ffsll((long long)m) - 1) : j0;
            m &= m - 1;                       // m==0 stays 0
            const float k1 = two ? 1.f : 0.f;

            const float4 A0 = tabA[j0][al];
            const float2 B0 = tabB[j0][al];
            const float4 A1 = tabA[j1][al];
            const float2 B1 = tabB[j1][al];

            const float t0 = gg - A0.x;
            const float t1 = gg - A1.x;
            const float E0 = ex2f((CM * t0) * t0);
            const float E1 = ex2f((CM * t1) * t1);
            const float wg0 = A0.y * E0;
            const float wg1 = (A1.y * k1) * E1;
            const float s0  = fmaf(wg0 * A0.z, t0, wg0);
            const float s1  = fmaf(wg1 * A1.z, t1, wg1);
            wv += wg0 + wg1;
            xv = fmaf(s0, A0.w, fmaf(s1, A1.w, xv));
            yv = fmaf(s0, B0.x, fmaf(s1, B1.x, yv));
            zv = fmaf(s0, B0.y, fmaf(s1, B1.y, zv));
        }

        // mbtr: coalesced RED.ADD per warp per segment.
        atomicAdd(mb + e * NG, wv);
        acc[e][lane][al * 3 + 0] = xv;
        acc[e][lane][al * 3 + 1] = yv;
        acc[e][lane][al * 3 + 2] = zv;
    }
    __syncthreads();

    // Transposed div store: 16 slots x 32 g x 24 floats; thread owns 3 cells.
    int gq[3], qq[3];
    float av[3][NE];
    bool  pe[3][NE];
    #pragma unroll
    for (int k = 0; k < 3; k++) {
        const int f = k * NTHR + t;
        gq[k] = f / ROWQ;
        qq[k] = f - gq[k] * ROWQ;
        const int zaq = zs[third * ATH + qq[k] / 3];
        #pragma unroll
        for (int e = 0; e < NE; e++) {
            av[k][e] = acc[e][gq[k]][qq[k]];
            pe[k][e] = (zaq == e);
        }
    }
    float* __restrict__ dbase = out + MBTR_SZ
        + ((size_t)(b * NE * NE) * NG + gchunk * GC) * (NA * 3)
        + third * ROWQ;

    #pragma unroll
    for (int slot = 0; slot < NE * NE; slot++) {
        const int e1 = slot >> 2, e2 = slot & 3;
        float* const sb = dbase + (size_t)slot * (NG * NA * 3);
        #pragma unroll
        for (int k = 0; k < 3; k++) {
            const float v = (pe[k][e1] ? av[k][e2] : 0.f)
                          + (pe[k][e2] ? av[k][e1] : 0.f);
            sb[gq[k] * (NA * 3) + qq[k]] = v;
        }
    }
}

extern "C" void kernel_launch(void* const* d_in, const int* in_sizes, int n_in,
                              void* d_out, int out_size)
{
    const float* r    = (const float*)d_in[0];
    const int*   z    = (const int*)  d_in[1];
    const float* grid = (const float*)d_in[2];
    float*       out  = (float*)d_out;

    zero_mbtr<<<MBTR_SZ / 4096, 1024>>>((float4*)out);
    mbtr_kernel<<<NBLK, NTHR>>>(r, z, grid, out);
}